// round 6
// baseline (speedup 1.0000x reference)
#include <cuda_runtime.h>
#include <cuda_bf16.h>
#include <cstdint>

#define D1 256
#define D2 128
#define K_DIM 256

static const int MAX_N = 100000;
static const int MAX_E = 1600000;

// fp32 scratch
__device__ float g_y1[MAX_N * D1];
__device__ float g_z1[MAX_N * D1];
__device__ float g_agg1[MAX_N * D1];
__device__ float g_y2[MAX_N * D2];
__device__ float g_z2[MAX_N * D2];
__device__ float g_agg2[MAX_N * D2];
__device__ float g_deg[MAX_N];
// bf16 split scratch
__device__ __nv_bfloat16 g_xhi[MAX_N * D1];
__device__ __nv_bfloat16 g_xlo[MAX_N * D1];
__device__ __nv_bfloat16 g_hhi[MAX_N * D1];
__device__ __nv_bfloat16 g_hlo[MAX_N * D1];
// weight splits
__device__ __nv_bfloat16 g_w[6 * 65536];
// CSR
__device__ int g_rowptr[MAX_N];
__device__ int g_cursor[MAX_N];
__device__ int g_csr[MAX_E];
__device__ int g_bsum[128];
__device__ int g_boff[128];

#define SCAN_BLK 1024

// ---------------------------------------------------------------------------
__device__ __forceinline__ uint32_t smem_to_u32(const void* p) {
    uint32_t a;
    asm("{ .reg .u64 t; cvta.to.shared.u64 t, %1; cvt.u32.u64 %0, t; }"
        : "=r"(a) : "l"(p));
    return a;
}

__device__ __forceinline__ void cp_async16(uint32_t saddr, const void* gaddr, uint32_t n) {
    asm volatile("cp.async.cg.shared.global [%0], [%1], 16, %2;"
                 :: "r"(saddr), "l"(gaddr), "r"(n) : "memory");
}

__device__ __forceinline__ void mma_bf16(float* c, const uint32_t* a, const uint32_t* b) {
    asm volatile(
        "mma.sync.aligned.m16n8k16.row.col.f32.bf16.bf16.f32 "
        "{%0,%1,%2,%3}, {%4,%5,%6,%7}, {%8,%9}, {%0,%1,%2,%3};"
        : "+f"(c[0]), "+f"(c[1]), "+f"(c[2]), "+f"(c[3])
        : "r"(a[0]), "r"(a[1]), "r"(a[2]), "r"(a[3]), "r"(b[0]), "r"(b[1]));
}

#define LDSM_X4(r, addr) \
    asm volatile("ldmatrix.sync.aligned.m8n8.x4.shared.b16 {%0,%1,%2,%3}, [%4];" \
                 : "=r"((r)[0]), "=r"((r)[1]), "=r"((r)[2]), "=r"((r)[3]) \
                 : "r"(addr))

#define GEMM_BAR() asm volatile("bar.sync 1, 256;" ::: "memory")

// ---------------------------------------------------------------------------
// Warp-specialized fused kernel.
//  Warps 0-7 : bf16x3 GEMM, 128x128 output tile. C = A@W^T (+bias).
//              A given as (hi,lo) bf16, K=256. W rows n0..n0+127.
//  Warps 8-15: CSR gather of `gin` -> raw sums into `gout` (GD cols).
//              GD=256: one warp per (node, 128-col half); GD=128: per node.
// ---------------------------------------------------------------------------
#define ROWB 80
#define S_AHI 0
#define S_ALO (128 * ROWB)
#define S_BHI (256 * ROWB)
#define S_BLO (384 * ROWB)
#define STAGE_SZ (512 * ROWB)          // 40960
#define FUSED_SMEM (3 * STAGE_SZ)      // 122880

template <int GD>
__global__ __launch_bounds__(512, 1)
void fused_gemm_gather(const __nv_bfloat16* __restrict__ Ahi,
                       const __nv_bfloat16* __restrict__ Alo,
                       const __nv_bfloat16* __restrict__ Whi,
                       const __nv_bfloat16* __restrict__ Wlo,
                       const float* __restrict__ bias,
                       float* __restrict__ C, int ldc, int ncb, int M,
                       const float* __restrict__ gin,
                       const int* __restrict__ rowptr,
                       const int* __restrict__ csr,
                       const float* __restrict__ deg,
                       float* __restrict__ gout, int gitems) {
    extern __shared__ char smem[];
    const int tid = threadIdx.x;
    const int wid = tid >> 5, lane = tid & 31;

    if (wid >= 8) {
        // ---------------- gather half ----------------
        if (!gitems) return;
        const int stride = gridDim.x * 8;
        for (int it = (int)blockIdx.x * 8 + (wid - 8); it < gitems; it += stride) {
            int node, c0;
            if (GD == 256) { node = it >> 1; c0 = (it & 1) * 128; }
            else           { node = it;      c0 = 0; }
            int start = rowptr[node];
            int cnt = (int)deg[node];
            float4 acc = make_float4(0.f, 0.f, 0.f, 0.f);
            for (int j0 = 0; j0 < cnt; j0 += 32) {
                int m = min(32, cnt - j0);
                int sid = (lane < m) ? csr[start + j0 + lane] : 0;
                for (int t = 0; t < m; t++) {
                    int sN = __shfl_sync(0xffffffff, sid, t);
                    float4 v = *(const float4*)(gin + (size_t)sN * GD + c0 + lane * 4);
                    acc.x += v.x; acc.y += v.y; acc.z += v.z; acc.w += v.w;
                }
            }
            *(float4*)(gout + (size_t)node * GD + c0 + lane * 4) = acc;
        }
        return;
    }

    // ---------------- GEMM half (warps 0-7, 256 threads) ----------------
    const uint32_t sbase = smem_to_u32(smem);
    const int m0 = ((int)blockIdx.x / ncb) * 128;
    const int n0 = ((int)blockIdx.x % ncb) * 128;
    const int wr = wid >> 2;     // 0..1 : 64-row block
    const int wc = wid & 3;      // 0..3 : 32-col block
    const __nv_bfloat16* Wh = Whi + (size_t)n0 * K_DIM;
    const __nv_bfloat16* Wl = Wlo + (size_t)n0 * K_DIM;

    float acc[4][4][4];
#pragma unroll
    for (int i = 0; i < 4; i++)
#pragma unroll
        for (int j = 0; j < 4; j++)
#pragma unroll
            for (int k = 0; k < 4; k++) acc[i][j][k] = 0.0f;

    auto issue = [&](int c, int stage) {
        const uint32_t s0 = sbase + (uint32_t)stage * STAGE_SZ;
        const int ke = c * 32;
#pragma unroll
        for (int i = 0; i < 2; i++) {
            int id = tid + i * 256;
            int row = id >> 2, cc = id & 3;
            int gm = m0 + row;
            uint32_t p = (gm < M) ? 16u : 0u;
            const size_t goff = (size_t)gm * K_DIM + ke + cc * 8;
            cp_async16(s0 + S_AHI + row * ROWB + cc * 16, Ahi + goff, p);
            cp_async16(s0 + S_ALO + row * ROWB + cc * 16, Alo + goff, p);
        }
#pragma unroll
        for (int i = 0; i < 2; i++) {
            int id = tid + i * 256;
            int row = id >> 2, cc = id & 3;
            const size_t goff = (size_t)row * K_DIM + ke + cc * 8;
            cp_async16(s0 + S_BHI + row * ROWB + cc * 16, Wh + goff, 16u);
            cp_async16(s0 + S_BLO + row * ROWB + cc * 16, Wl + goff, 16u);
        }
        asm volatile("cp.async.commit_group;" ::: "memory");
    };

    issue(0, 0);
    issue(1, 1);

    for (int c = 0; c < 8; c++) {
        asm volatile("cp.async.wait_group 1;" ::: "memory");
        GEMM_BAR();
        if (c + 2 < 8) issue(c + 2, (c + 2) % 3);

        const uint32_t s0 = sbase + (uint32_t)(c % 3) * STAGE_SZ;
#pragma unroll
        for (int s = 0; s < 2; s++) {
            const uint32_t aoff = s0 + (uint32_t)(wr * 64 + (lane & 15)) * ROWB
                                  + ((lane >> 4) << 4) + s * 32;
            const uint32_t boff = s0 + S_BHI
                                  + (uint32_t)(wc * 32 + (lane & 7) + ((lane >> 4) << 3)) * ROWB
                                  + (((lane >> 3) & 1) << 4) + s * 32;
            uint32_t ahi[4][4], alo[4][4], bb[2][4];
#pragma unroll
            for (int mi = 0; mi < 4; mi++) {
                LDSM_X4(ahi[mi], aoff + S_AHI + mi * (16 * ROWB));
                LDSM_X4(alo[mi], aoff + (S_ALO - S_AHI) + mi * (16 * ROWB));
            }
#pragma unroll
            for (int p = 0; p < 2; p++) LDSM_X4(bb[p], boff + p * (16 * ROWB));
#pragma unroll
            for (int mi = 0; mi < 4; mi++)
#pragma unroll
                for (int p = 0; p < 2; p++) {
                    mma_bf16(acc[mi][2 * p],     ahi[mi], &bb[p][0]);
                    mma_bf16(acc[mi][2 * p + 1], ahi[mi], &bb[p][2]);
                    mma_bf16(acc[mi][2 * p],     alo[mi], &bb[p][0]);
                    mma_bf16(acc[mi][2 * p + 1], alo[mi], &bb[p][2]);
                }
#pragma unroll
            for (int p = 0; p < 2; p++) LDSM_X4(bb[p], boff + (S_BLO - S_BHI) + p * (16 * ROWB));
#pragma unroll
            for (int mi = 0; mi < 4; mi++)
#pragma unroll
                for (int p = 0; p < 2; p++) {
                    mma_bf16(acc[mi][2 * p],     ahi[mi], &bb[p][0]);
                    mma_bf16(acc[mi][2 * p + 1], ahi[mi], &bb[p][2]);
                }
        }
        GEMM_BAR();
    }

    // epilogue
#pragma unroll
    for (int mi = 0; mi < 4; mi++) {
        int r0 = m0 + wr * 64 + mi * 16 + (lane >> 2);
        int r1 = r0 + 8;
#pragma unroll
        for (int ni = 0; ni < 4; ni++) {
            int col = n0 + wc * 32 + ni * 8 + 2 * (lane & 3);
            float bx = 0.f, by = 0.f;
            if (bias) { bx = __ldg(bias + col); by = __ldg(bias + col + 1); }
            if (r0 < M)
                *(float2*)(C + (size_t)r0 * ldc + col) =
                    make_float2(acc[mi][ni][0] + bx, acc[mi][ni][1] + by);
            if (r1 < M)
                *(float2*)(C + (size_t)r1 * ldc + col) =
                    make_float2(acc[mi][ni][2] + bx, acc[mi][ni][3] + by);
        }
    }
}

// ---------------------------------------------------------------------------
// splits
// ---------------------------------------------------------------------------
__device__ __forceinline__ void split1(float v, __nv_bfloat16& h, __nv_bfloat16& l) {
    h = __float2bfloat16(v);
    l = __float2bfloat16(v - __bfloat162float(h));
}

__global__ void split_kernel(const float* __restrict__ in,
                             __nv_bfloat16* __restrict__ hi,
                             __nv_bfloat16* __restrict__ lo, int n4) {
    int i = blockIdx.x * blockDim.x + threadIdx.x;
    if (i >= n4) return;
    float4 v = ((const float4*)in)[i];
    __nv_bfloat16 h0, h1, h2, h3, l0, l1, l2, l3;
    split1(v.x, h0, l0); split1(v.y, h1, l1);
    split1(v.z, h2, l2); split1(v.w, h3, l3);
    ((__nv_bfloat162*)hi)[2 * i]     = __nv_bfloat162(h0, h1);
    ((__nv_bfloat162*)hi)[2 * i + 1] = __nv_bfloat162(h2, h3);
    ((__nv_bfloat162*)lo)[2 * i]     = __nv_bfloat162(l0, l1);
    ((__nv_bfloat162*)lo)[2 * i + 1] = __nv_bfloat162(l2, l3);
}

__global__ void wsplit_all(const float* __restrict__ W1l, const float* __restrict__ W1r,
                           const float* __restrict__ W2l, const float* __restrict__ W2r,
                           __nv_bfloat16* __restrict__ w) {
    int i = blockIdx.x * blockDim.x + threadIdx.x;
    const float* src;
    __nv_bfloat16 *hi, *lo;
    int base;
    if (i < 16384)      { src = W1l; base = i;          hi = w;               lo = w + 65536; }
    else if (i < 32768) { src = W1r; base = i - 16384;  hi = w + 2 * 65536;   lo = w + 3 * 65536; }
    else if (i < 40960) { src = W2l; base = i - 32768;  hi = w + 4 * 65536;   lo = w + 5 * 65536; }
    else if (i < 49152) { src = W2r; base = i - 40960;  hi = w + 4 * 65536 + 32768; lo = w + 5 * 65536 + 32768; }
    else return;
    float4 v = ((const float4*)src)[base];
    __nv_bfloat16 h0, h1, h2, h3, l0, l1, l2, l3;
    split1(v.x, h0, l0); split1(v.y, h1, l1);
    split1(v.z, h2, l2); split1(v.w, h3, l3);
    ((__nv_bfloat162*)hi)[2 * base]     = __nv_bfloat162(h0, h1);
    ((__nv_bfloat162*)hi)[2 * base + 1] = __nv_bfloat162(h2, h3);
    ((__nv_bfloat162*)lo)[2 * base]     = __nv_bfloat162(l0, l1);
    ((__nv_bfloat162*)lo)[2 * base + 1] = __nv_bfloat162(l2, l3);
}

// ---------------------------------------------------------------------------
// degree + CSR build
// ---------------------------------------------------------------------------
__global__ void zero_deg(float* __restrict__ deg, int N) {
    int i = blockIdx.x * blockDim.x + threadIdx.x;
    if (i < N) deg[i] = 0.0f;
}

__global__ void deg_kernel(const int* __restrict__ dst, float* __restrict__ deg, int E) {
    int i = blockIdx.x * blockDim.x + threadIdx.x;
    if (i < E) atomicAdd(&deg[dst[i]], 1.0f);
}

__global__ void scan_part(const float* __restrict__ deg, int* __restrict__ bsum, int N) {
    __shared__ int sm[256];
    int b = blockIdx.x, t = threadIdx.x;
    int s = 0;
#pragma unroll
    for (int k = 0; k < 4; k++) {
        int i = b * SCAN_BLK + t * 4 + k;
        if (i < N) s += (int)deg[i];
    }
    sm[t] = s;
    __syncthreads();
    for (int o = 128; o > 0; o >>= 1) {
        if (t < o) sm[t] += sm[t + o];
        __syncthreads();
    }
    if (t == 0) bsum[b] = sm[0];
}

__global__ void scan_sums(const int* __restrict__ bsum, int* __restrict__ boff, int nb) {
    __shared__ int sm[128];
    int t = threadIdx.x;
    sm[t] = (t < nb) ? bsum[t] : 0;
    __syncthreads();
    for (int o = 1; o < 128; o <<= 1) {
        int v = (t >= o) ? sm[t - o] : 0;
        __syncthreads();
        sm[t] += v;
        __syncthreads();
    }
    if (t < nb) boff[t] = (t == 0) ? 0 : sm[t - 1];
}

__global__ void scan_write(const float* __restrict__ deg, const int* __restrict__ boff,
                           int* __restrict__ rowptr, int* __restrict__ cursor, int N) {
    __shared__ int sm[256];
    int b = blockIdx.x, t = threadIdx.x;
    int d[4];
    int s = 0;
#pragma unroll
    for (int k = 0; k < 4; k++) {
        int i = b * SCAN_BLK + t * 4 + k;
        d[k] = (i < N) ? (int)deg[i] : 0;
        s += d[k];
    }
    sm[t] = s;
    __syncthreads();
    for (int o = 1; o < 256; o <<= 1) {
        int v = (t >= o) ? sm[t - o] : 0;
        __syncthreads();
        sm[t] += v;
        __syncthreads();
    }
    int off = boff[b] + ((t == 0) ? 0 : sm[t - 1]);
#pragma unroll
    for (int k = 0; k < 4; k++) {
        int i = b * SCAN_BLK + t * 4 + k;
        if (i < N) { rowptr[i] = off; cursor[i] = off; }
        off += d[k];
    }
}

__global__ void fill_csr(const int* __restrict__ src, const int* __restrict__ dst,
                         int* __restrict__ cursor, int* __restrict__ csr, int E) {
    int i = blockIdx.x * blockDim.x + threadIdx.x;
    if (i >= E) return;
    int pos = atomicAdd(&cursor[dst[i]], 1);
    csr[pos] = src[i];
}

// ---------------------------------------------------------------------------
// combines
// ---------------------------------------------------------------------------
template <int DQ>
__global__ void combine_split_kernel(const float* __restrict__ agg,
                                     const float* __restrict__ z,
                                     const float* __restrict__ deg,
                                     __nv_bfloat16* __restrict__ hhi,
                                     __nv_bfloat16* __restrict__ hlo, int total4) {
    int i = blockIdx.x * blockDim.x + threadIdx.x;
    if (i >= total4) return;
    int row = i / DQ;
    float sc = 1.0f / fmaxf(deg[row], 1.0f);
    float4 a = ((const float4*)agg)[i];
    float4 zz = ((const float4*)z)[i];
    float4 r;
    r.x = fmaxf(a.x * sc + zz.x, 0.f);
    r.y = fmaxf(a.y * sc + zz.y, 0.f);
    r.z = fmaxf(a.z * sc + zz.z, 0.f);
    r.w = fmaxf(a.w * sc + zz.w, 0.f);
    __nv_bfloat16 h0, h1, h2, h3, l0, l1, l2, l3;
    split1(r.x, h0, l0); split1(r.y, h1, l1);
    split1(r.z, h2, l2); split1(r.w, h3, l3);
    ((__nv_bfloat162*)hhi)[2 * i]     = __nv_bfloat162(h0, h1);
    ((__nv_bfloat162*)hhi)[2 * i + 1] = __nv_bfloat162(h2, h3);
    ((__nv_bfloat162*)hlo)[2 * i]     = __nv_bfloat162(l0, l1);
    ((__nv_bfloat162*)hlo)[2 * i + 1] = __nv_bfloat162(l2, l3);
}

template <int DQ>
__global__ void combine_final_kernel(const float* __restrict__ agg,
                                     const float* __restrict__ z,
                                     const float* __restrict__ deg,
                                     float* __restrict__ out, int total4) {
    int i = blockIdx.x * blockDim.x + threadIdx.x;
    if (i >= total4) return;
    int row = i / DQ;
    float sc = 1.0f / fmaxf(deg[row], 1.0f);
    float4 a = ((const float4*)agg)[i];
    float4 zz = ((const float4*)z)[i];
    ((float4*)out)[i] = make_float4(a.x * sc + zz.x, a.y * sc + zz.y,
                                    a.z * sc + zz.z, a.w * sc + zz.w);
}

// ---------------------------------------------------------------------------
extern "C" void kernel_launch(void* const* d_in, const int* in_sizes, int n_in,
                              void* d_out, int out_size) {
    const float* x    = (const float*)d_in[0];
    const int* eidx   = (const int*)d_in[1];
    const float* W1l  = (const float*)d_in[2];
    const float* b1   = (const float*)d_in[3];
    const float* W1r  = (const float*)d_in[4];
    const float* W2l  = (const float*)d_in[5];
    const float* b2   = (const float*)d_in[6];
    const float* W2r  = (const float*)d_in[7];
    float* out = (float*)d_out;

    const int N = in_sizes[0] / D1;
    const int E = in_sizes[1] / 2;
    const int* src = eidx;
    const int* dst = eidx + E;

    float *y1, *z1, *agg1, *y2, *z2, *agg2, *deg;
    __nv_bfloat16 *xhi, *xlo, *hhi, *hlo, *w;
    int *rowptr, *cursor, *csr, *bsum, *boff;
    cudaGetSymbolAddress((void**)&y1,   g_y1);
    cudaGetSymbolAddress((void**)&z1,   g_z1);
    cudaGetSymbolAddress((void**)&agg1, g_agg1);
    cudaGetSymbolAddress((void**)&y2,   g_y2);
    cudaGetSymbolAddress((void**)&z2,   g_z2);
    cudaGetSymbolAddress((void**)&agg2, g_agg2);
    cudaGetSymbolAddress((void**)&deg,  g_deg);
    cudaGetSymbolAddress((void**)&xhi,  g_xhi);
    cudaGetSymbolAddress((void**)&xlo,  g_xlo);
    cudaGetSymbolAddress((void**)&hhi,  g_hhi);
    cudaGetSymbolAddress((void**)&hlo,  g_hlo);
    cudaGetSymbolAddress((void**)&w,    g_w);
    cudaGetSymbolAddress((void**)&rowptr, g_rowptr);
    cudaGetSymbolAddress((void**)&cursor, g_cursor);
    cudaGetSymbolAddress((void**)&csr,    g_csr);
    cudaGetSymbolAddress((void**)&bsum,   g_bsum);
    cudaGetSymbolAddress((void**)&boff,   g_boff);

    __nv_bfloat16* w1l_hi = w;
    __nv_bfloat16* w1l_lo = w + 65536;
    __nv_bfloat16* w1r_hi = w + 2 * 65536;
    __nv_bfloat16* w1r_lo = w + 3 * 65536;
    __nv_bfloat16* w2l_hi = w + 4 * 65536;
    __nv_bfloat16* w2l_lo = w + 5 * 65536;
    __nv_bfloat16* w2r_hi = w + 4 * 65536 + 32768;
    __nv_bfloat16* w2r_lo = w + 5 * 65536 + 32768;

    cudaFuncSetAttribute(fused_gemm_gather<256>,
                         cudaFuncAttributeMaxDynamicSharedMemorySize, FUSED_SMEM);
    cudaFuncSetAttribute(fused_gemm_gather<128>,
                         cudaFuncAttributeMaxDynamicSharedMemorySize, FUSED_SMEM);

    const int mb = (N + 127) / 128;          // 782
    const int nb = (N + SCAN_BLK - 1) / SCAN_BLK;

    // 1-2: degree
    zero_deg<<<(N + 255) / 256, 256>>>(deg, N);
    deg_kernel<<<(E + 255) / 256, 256>>>(dst, deg, E);
    // 3-4: splits
    split_kernel<<<(N * (D1 / 4) + 255) / 256, 256>>>(x, xhi, xlo, N * (D1 / 4));
    wsplit_all<<<(49152 + 255) / 256, 256>>>(W1l, W1r, W2l, W2r, w);
    // 5: y1 = x@W1l^T  (no gather)  — ncu capture target
    fused_gemm_gather<256><<<2 * mb, 512, FUSED_SMEM>>>(
        xhi, xlo, w1l_hi, w1l_lo, nullptr, y1, D1, 2, N,
        nullptr, nullptr, nullptr, nullptr, nullptr, 0);
    // 6-9: CSR build
    scan_part<<<nb, 256>>>(deg, bsum, N);
    scan_sums<<<1, 128>>>(bsum, boff, nb);
    scan_write<<<nb, 256>>>(deg, boff, rowptr, cursor, N);
    fill_csr<<<(E + 255) / 256, 256>>>(src, dst, cursor, csr, E);
    // 10: z1 = x@W1r^T + b1  ||  gather y1 -> agg1
    fused_gemm_gather<256><<<2 * mb, 512, FUSED_SMEM>>>(
        xhi, xlo, w1r_hi, w1r_lo, b1, z1, D1, 2, N,
        y1, rowptr, csr, deg, agg1, 2 * N);
    // 11: h = relu(agg1/deg + z1) -> bf16 hi/lo
    int t1 = N * (D1 / 4);
    combine_split_kernel<D1 / 4><<<(t1 + 255) / 256, 256>>>(agg1, z1, deg, hhi, hlo, t1);
    // 12: y2 = h@W2l^T
    fused_gemm_gather<128><<<mb, 512, FUSED_SMEM>>>(
        hhi, hlo, w2l_hi, w2l_lo, nullptr, y2, D2, 1, N,
        nullptr, nullptr, nullptr, nullptr, nullptr, 0);
    // 13: z2 = h@W2r^T + b2  ||  gather y2 -> agg2
    fused_gemm_gather<128><<<mb, 512, FUSED_SMEM>>>(
        hhi, hlo, w2r_hi, w2r_lo, b2, z2, D2, 1, N,
        y2, rowptr, csr, deg, agg2, N);
    // 14: out = agg2/deg + z2
    int t2 = N * (D2 / 4);
    combine_final_kernel<D2 / 4><<<(t2 + 255) / 256, 256>>>(agg2, z2, deg, out, t2);
}

// round 7
// speedup vs baseline: 1.6032x; 1.6032x over previous
#include <cuda_runtime.h>
#include <cuda_bf16.h>
#include <cstdint>

#define D1 256
#define D2 128
#define K_DIM 256

static const int MAX_N = 100000;
static const int MAX_E = 1600000;

// fp32 scratch
__device__ float g_y1[MAX_N * D1];
__device__ float g_z1[MAX_N * D1];
__device__ float g_y2[MAX_N * D2];
__device__ float g_z2[MAX_N * D2];
__device__ float g_deg[MAX_N];
// bf16 split scratch
__device__ __nv_bfloat16 g_xhi[MAX_N * D1];
__device__ __nv_bfloat16 g_xlo[MAX_N * D1];
__device__ __nv_bfloat16 g_hhi[MAX_N * D1];
__device__ __nv_bfloat16 g_hlo[MAX_N * D1];
// weight splits
__device__ __nv_bfloat16 g_w[6 * 65536];
// CSR
__device__ int g_rowptr[MAX_N];
__device__ int g_cursor[MAX_N];
__device__ int g_csr[MAX_E];
__device__ int g_bsum[128];
__device__ int g_boff[128];

#define SCAN_BLK 1024

// ---------------------------------------------------------------------------
__device__ __forceinline__ uint32_t smem_to_u32(const void* p) {
    uint32_t a;
    asm("{ .reg .u64 t; cvta.to.shared.u64 t, %1; cvt.u32.u64 %0, t; }"
        : "=r"(a) : "l"(p));
    return a;
}

__device__ __forceinline__ void cp_async16(uint32_t saddr, const void* gaddr, uint32_t n) {
    asm volatile("cp.async.cg.shared.global [%0], [%1], 16, %2;"
                 :: "r"(saddr), "l"(gaddr), "r"(n) : "memory");
}

__device__ __forceinline__ void mma_bf16(float* c, const uint32_t* a, const uint32_t* b) {
    asm volatile(
        "mma.sync.aligned.m16n8k16.row.col.f32.bf16.bf16.f32 "
        "{%0,%1,%2,%3}, {%4,%5,%6,%7}, {%8,%9}, {%0,%1,%2,%3};"
        : "+f"(c[0]), "+f"(c[1]), "+f"(c[2]), "+f"(c[3])
        : "r"(a[0]), "r"(a[1]), "r"(a[2]), "r"(a[3]), "r"(b[0]), "r"(b[1]));
}

#define LDSM_X4(r, addr) \
    asm volatile("ldmatrix.sync.aligned.m8n8.x4.shared.b16 {%0,%1,%2,%3}, [%4];" \
                 : "=r"((r)[0]), "=r"((r)[1]), "=r"((r)[2]), "=r"((r)[3]) \
                 : "r"(addr))

// ---------------------------------------------------------------------------
// bf16x3 GEMM, 128 rows x 256 cols per CTA, 3-stage cp.async pipeline,
// single __syncthreads per K-chunk. 3 MMA terms per chunk.
// ---------------------------------------------------------------------------
#define ROWB 80
#define AHI_OFF 0
#define ALO_OFF (128 * ROWB)
#define BHI_OFF (256 * ROWB)
#define BLO_OFF (512 * ROWB)
#define STAGE_SZ (768 * ROWB)          // 61440
#define GEMM_SMEM (3 * STAGE_SZ)       // 184320

__global__ __launch_bounds__(256, 1)
void gemm3(const __nv_bfloat16* __restrict__ Ahi,
           const __nv_bfloat16* __restrict__ Alo,
           const __nv_bfloat16* __restrict__ Whi,   // 256 rows x 256
           const __nv_bfloat16* __restrict__ Wlo,
           float* __restrict__ outA, int ldA, const float* __restrict__ biasA,
           float* __restrict__ outB, int ldB, const float* __restrict__ biasB,
           int M) {
    extern __shared__ char smem[];
    const uint32_t sbase = smem_to_u32(smem);
    const int tid = threadIdx.x;
    const int wid = tid >> 5, lane = tid & 31;
    const int wr = wid >> 2;
    const int wc = wid & 3;
    const int m0 = (int)blockIdx.x * 128;

    float acc[4][8][4];
#pragma unroll
    for (int i = 0; i < 4; i++)
#pragma unroll
        for (int j = 0; j < 8; j++)
#pragma unroll
            for (int k = 0; k < 4; k++) acc[i][j][k] = 0.0f;

    auto issue = [&](int c, int stage) {
        const uint32_t s0 = sbase + (uint32_t)stage * STAGE_SZ;
        const int ke = c * 32;
#pragma unroll
        for (int i = 0; i < 2; i++) {
            int id = tid + i * 256;
            int row = id >> 2, cc = id & 3;
            int gm = m0 + row;
            uint32_t p = (gm < M) ? 16u : 0u;
            const size_t goff = (size_t)gm * K_DIM + ke + cc * 8;
            cp_async16(s0 + AHI_OFF + row * ROWB + cc * 16, Ahi + goff, p);
            cp_async16(s0 + ALO_OFF + row * ROWB + cc * 16, Alo + goff, p);
        }
#pragma unroll
        for (int i = 0; i < 4; i++) {
            int id = tid + i * 256;
            int row = id >> 2, cc = id & 3;
            const size_t goff = (size_t)row * K_DIM + ke + cc * 8;
            cp_async16(s0 + BHI_OFF + row * ROWB + cc * 16, Whi + goff, 16u);
            cp_async16(s0 + BLO_OFF + row * ROWB + cc * 16, Wlo + goff, 16u);
        }
        asm volatile("cp.async.commit_group;" ::: "memory");
    };

    issue(0, 0);
    issue(1, 1);

    for (int c = 0; c < 8; c++) {
        asm volatile("cp.async.wait_group 1;" ::: "memory");
        __syncthreads();
        if (c + 2 < 8) issue(c + 2, (c + 2) % 3);

        const uint32_t s0 = sbase + (uint32_t)(c % 3) * STAGE_SZ;
#pragma unroll
        for (int s = 0; s < 2; s++) {
            const uint32_t aoff = s0 + (uint32_t)(wr * 64 + (lane & 15)) * ROWB
                                  + ((lane >> 4) << 4) + s * 32;
            const uint32_t boff = s0 + BHI_OFF
                                  + (uint32_t)(wc * 64 + (lane & 7) + ((lane >> 4) << 3)) * ROWB
                                  + (((lane >> 3) & 1) << 4) + s * 32;
            uint32_t ahi[4][4], alo[4][4], bb[4][4];
#pragma unroll
            for (int mi = 0; mi < 4; mi++) {
                LDSM_X4(ahi[mi], aoff + AHI_OFF + mi * (16 * ROWB));
                LDSM_X4(alo[mi], aoff + ALO_OFF + mi * (16 * ROWB));
            }
#pragma unroll
            for (int p = 0; p < 4; p++) LDSM_X4(bb[p], boff + p * (16 * ROWB));
#pragma unroll
            for (int mi = 0; mi < 4; mi++)
#pragma unroll
                for (int p = 0; p < 4; p++) {
                    mma_bf16(acc[mi][2 * p],     ahi[mi], &bb[p][0]);
                    mma_bf16(acc[mi][2 * p + 1], ahi[mi], &bb[p][2]);
                    mma_bf16(acc[mi][2 * p],     alo[mi], &bb[p][0]);
                    mma_bf16(acc[mi][2 * p + 1], alo[mi], &bb[p][2]);
                }
#pragma unroll
            for (int p = 0; p < 4; p++) LDSM_X4(bb[p], boff + (BLO_OFF - BHI_OFF) + p * (16 * ROWB));
#pragma unroll
            for (int mi = 0; mi < 4; mi++)
#pragma unroll
                for (int p = 0; p < 4; p++) {
                    mma_bf16(acc[mi][2 * p],     ahi[mi], &bb[p][0]);
                    mma_bf16(acc[mi][2 * p + 1], ahi[mi], &bb[p][2]);
                }
        }
    }

    const bool isB = (wc >= 2);
    float* out = isB ? outB : outA;
    const int ld = isB ? ldB : ldA;
    const float* bias = isB ? biasB : biasA;
    const int cbase = wc * 64 - (isB ? 128 : 0);

#pragma unroll
    for (int mi = 0; mi < 4; mi++) {
        int r0 = m0 + wr * 64 + mi * 16 + (lane >> 2);
        int r1 = r0 + 8;
#pragma unroll
        for (int ni = 0; ni < 8; ni++) {
            int col = cbase + ni * 8 + 2 * (lane & 3);
            float bx = 0.f, by = 0.f;
            if (bias) { bx = __ldg(bias + col); by = __ldg(bias + col + 1); }
            if (r0 < M)
                *(float2*)(out + (size_t)r0 * ld + col) =
                    make_float2(acc[mi][ni][0] + bx, acc[mi][ni][1] + by);
            if (r1 < M)
                *(float2*)(out + (size_t)r1 * ld + col) =
                    make_float2(acc[mi][ni][2] + bx, acc[mi][ni][3] + by);
        }
    }
}

// ---------------------------------------------------------------------------
// splits
// ---------------------------------------------------------------------------
__device__ __forceinline__ void split1(float v, __nv_bfloat16& h, __nv_bfloat16& l) {
    h = __float2bfloat16(v);
    l = __float2bfloat16(v - __bfloat162float(h));
}

__global__ void split_kernel(const float* __restrict__ in,
                             __nv_bfloat16* __restrict__ hi,
                             __nv_bfloat16* __restrict__ lo, int n4) {
    int i = blockIdx.x * blockDim.x + threadIdx.x;
    if (i >= n4) return;
    float4 v = ((const float4*)in)[i];
    __nv_bfloat16 h0, h1, h2, h3, l0, l1, l2, l3;
    split1(v.x, h0, l0); split1(v.y, h1, l1);
    split1(v.z, h2, l2); split1(v.w, h3, l3);
    ((__nv_bfloat162*)hi)[2 * i]     = __nv_bfloat162(h0, h1);
    ((__nv_bfloat162*)hi)[2 * i + 1] = __nv_bfloat162(h2, h3);
    ((__nv_bfloat162*)lo)[2 * i]     = __nv_bfloat162(l0, l1);
    ((__nv_bfloat162*)lo)[2 * i + 1] = __nv_bfloat162(l2, l3);
}

__global__ void wsplit_all(const float* __restrict__ W1l, const float* __restrict__ W1r,
                           const float* __restrict__ W2l, const float* __restrict__ W2r,
                           __nv_bfloat16* __restrict__ w) {
    int i = blockIdx.x * blockDim.x + threadIdx.x;
    const float* src;
    __nv_bfloat16 *hi, *lo;
    int base;
    if (i < 16384)      { src = W1l; base = i;          hi = w;               lo = w + 65536; }
    else if (i < 32768) { src = W1r; base = i - 16384;  hi = w + 2 * 65536;   lo = w + 3 * 65536; }
    else if (i < 40960) { src = W2l; base = i - 32768;  hi = w + 4 * 65536;   lo = w + 5 * 65536; }
    else if (i < 49152) { src = W2r; base = i - 40960;  hi = w + 4 * 65536 + 32768; lo = w + 5 * 65536 + 32768; }
    else return;
    float4 v = ((const float4*)src)[base];
    __nv_bfloat16 h0, h1, h2, h3, l0, l1, l2, l3;
    split1(v.x, h0, l0); split1(v.y, h1, l1);
    split1(v.z, h2, l2); split1(v.w, h3, l3);
    ((__nv_bfloat162*)hi)[2 * base]     = __nv_bfloat162(h0, h1);
    ((__nv_bfloat162*)hi)[2 * base + 1] = __nv_bfloat162(h2, h3);
    ((__nv_bfloat162*)lo)[2 * base]     = __nv_bfloat162(l0, l1);
    ((__nv_bfloat162*)lo)[2 * base + 1] = __nv_bfloat162(l2, l3);
}

// ---------------------------------------------------------------------------
// degree + CSR build
// ---------------------------------------------------------------------------
__global__ void deg_kernel(const int* __restrict__ dst, float* __restrict__ deg, int E) {
    int i = blockIdx.x * blockDim.x + threadIdx.x;
    if (i < E) atomicAdd(&deg[dst[i]], 1.0f);
}

__global__ void scan_part(const float* __restrict__ deg, int* __restrict__ bsum, int N) {
    __shared__ int sm[256];
    int b = blockIdx.x, t = threadIdx.x;
    int s = 0;
#pragma unroll
    for (int k = 0; k < 4; k++) {
        int i = b * SCAN_BLK + t * 4 + k;
        if (i < N) s += (int)deg[i];
    }
    sm[t] = s;
    __syncthreads();
    for (int o = 128; o > 0; o >>= 1) {
        if (t < o) sm[t] += sm[t + o];
        __syncthreads();
    }
    if (t == 0) bsum[b] = sm[0];
}

__global__ void scan_sums(const int* __restrict__ bsum, int* __restrict__ boff, int nb) {
    __shared__ int sm[128];
    int t = threadIdx.x;
    sm[t] = (t < nb) ? bsum[t] : 0;
    __syncthreads();
    for (int o = 1; o < 128; o <<= 1) {
        int v = (t >= o) ? sm[t - o] : 0;
        __syncthreads();
        sm[t] += v;
        __syncthreads();
    }
    if (t < nb) boff[t] = (t == 0) ? 0 : sm[t - 1];
}

__global__ void scan_write(const float* __restrict__ deg, const int* __restrict__ boff,
                           int* __restrict__ rowptr, int* __restrict__ cursor, int N) {
    __shared__ int sm[256];
    int b = blockIdx.x, t = threadIdx.x;
    int d[4];
    int s = 0;
#pragma unroll
    for (int k = 0; k < 4; k++) {
        int i = b * SCAN_BLK + t * 4 + k;
        d[k] = (i < N) ? (int)deg[i] : 0;
        s += d[k];
    }
    sm[t] = s;
    __syncthreads();
    for (int o = 1; o < 256; o <<= 1) {
        int v = (t >= o) ? sm[t - o] : 0;
        __syncthreads();
        sm[t] += v;
        __syncthreads();
    }
    int off = boff[b] + ((t == 0) ? 0 : sm[t - 1]);
#pragma unroll
    for (int k = 0; k < 4; k++) {
        int i = b * SCAN_BLK + t * 4 + k;
        if (i < N) { rowptr[i] = off; cursor[i] = off; }
        off += d[k];
    }
}

__global__ void fill_csr(const int* __restrict__ src, const int* __restrict__ dst,
                         int* __restrict__ cursor, int* __restrict__ csr, int E) {
    int i = blockIdx.x * blockDim.x + threadIdx.x;
    if (i >= E) return;
    int pos = atomicAdd(&cursor[dst[i]], 1);
    csr[pos] = src[i];
}

// ---------------------------------------------------------------------------
// CSR gathers (combine fused)
// ---------------------------------------------------------------------------
__global__ void gather1(const float* __restrict__ y, const float* __restrict__ z,
                        const int* __restrict__ rowptr, const int* __restrict__ csr,
                        const float* __restrict__ deg,
                        __nv_bfloat16* __restrict__ hhi, __nv_bfloat16* __restrict__ hlo,
                        int N) {
    int gw = (blockIdx.x * blockDim.x + threadIdx.x) >> 5;
    int lane = threadIdx.x & 31;
    int node = gw >> 1;
    int c0 = (gw & 1) * 128;
    if (node >= N) return;

    int start = rowptr[node];
    float degf = deg[node];
    int cnt = (int)degf;
    float4 acc = make_float4(0.f, 0.f, 0.f, 0.f);
    for (int j0 = 0; j0 < cnt; j0 += 32) {
        int m = min(32, cnt - j0);
        int sid = (lane < m) ? csr[start + j0 + lane] : 0;
        for (int t = 0; t < m; t++) {
            int sN = __shfl_sync(0xffffffff, sid, t);
            float4 v = *(const float4*)(y + (size_t)sN * D1 + c0 + lane * 4);
            acc.x += v.x; acc.y += v.y; acc.z += v.z; acc.w += v.w;
        }
    }
    float sc = 1.0f / fmaxf(degf, 1.0f);
    float4 zz = *(const float4*)(z + (size_t)node * D1 + c0 + lane * 4);
    float4 r;
    r.x = fmaxf(acc.x * sc + zz.x, 0.f);
    r.y = fmaxf(acc.y * sc + zz.y, 0.f);
    r.z = fmaxf(acc.z * sc + zz.z, 0.f);
    r.w = fmaxf(acc.w * sc + zz.w, 0.f);
    __nv_bfloat16 h0, h1, h2, h3, l0, l1, l2, l3;
    split1(r.x, h0, l0); split1(r.y, h1, l1);
    split1(r.z, h2, l2); split1(r.w, h3, l3);
    size_t o = (size_t)node * D1 + c0 + lane * 4;
    *(__nv_bfloat162*)(hhi + o)     = __nv_bfloat162(h0, h1);
    *(__nv_bfloat162*)(hhi + o + 2) = __nv_bfloat162(h2, h3);
    *(__nv_bfloat162*)(hlo + o)     = __nv_bfloat162(l0, l1);
    *(__nv_bfloat162*)(hlo + o + 2) = __nv_bfloat162(l2, l3);
}

__global__ void gather2(const float* __restrict__ y, const float* __restrict__ z,
                        const int* __restrict__ rowptr, const int* __restrict__ csr,
                        const float* __restrict__ deg,
                        float* __restrict__ out, int N) {
    int node = (blockIdx.x * blockDim.x + threadIdx.x) >> 5;
    int lane = threadIdx.x & 31;
    if (node >= N) return;

    int start = rowptr[node];
    float degf = deg[node];
    int cnt = (int)degf;
    float4 acc = make_float4(0.f, 0.f, 0.f, 0.f);
    for (int j0 = 0; j0 < cnt; j0 += 32) {
        int m = min(32, cnt - j0);
        int sid = (lane < m) ? csr[start + j0 + lane] : 0;
        for (int t = 0; t < m; t++) {
            int sN = __shfl_sync(0xffffffff, sid, t);
            float4 v = *(const float4*)(y + (size_t)sN * D2 + lane * 4);
            acc.x += v.x; acc.y += v.y; acc.z += v.z; acc.w += v.w;
        }
    }
    float sc = 1.0f / fmaxf(degf, 1.0f);
    float4 zz = *(const float4*)(z + (size_t)node * D2 + lane * 4);
    *(float4*)(out + (size_t)node * D2 + lane * 4) =
        make_float4(acc.x * sc + zz.x, acc.y * sc + zz.y,
                    acc.z * sc + zz.z, acc.w * sc + zz.w);
}

// ---------------------------------------------------------------------------
extern "C" void kernel_launch(void* const* d_in, const int* in_sizes, int n_in,
                              void* d_out, int out_size) {
    const float* x    = (const float*)d_in[0];
    const int* eidx   = (const int*)d_in[1];
    const float* W1l  = (const float*)d_in[2];
    const float* b1   = (const float*)d_in[3];
    const float* W1r  = (const float*)d_in[4];
    const float* W2l  = (const float*)d_in[5];
    const float* b2   = (const float*)d_in[6];
    const float* W2r  = (const float*)d_in[7];
    float* out = (float*)d_out;

    const int N = in_sizes[0] / D1;
    const int E = in_sizes[1] / 2;
    const int* src = eidx;
    const int* dst = eidx + E;

    float *y1, *z1, *y2, *z2, *deg;
    __nv_bfloat16 *xhi, *xlo, *hhi, *hlo, *w;
    int *rowptr, *cursor, *csr, *bsum, *boff;
    cudaGetSymbolAddress((void**)&y1,   g_y1);
    cudaGetSymbolAddress((void**)&z1,   g_z1);
    cudaGetSymbolAddress((void**)&y2,   g_y2);
    cudaGetSymbolAddress((void**)&z2,   g_z2);
    cudaGetSymbolAddress((void**)&deg,  g_deg);
    cudaGetSymbolAddress((void**)&xhi,  g_xhi);
    cudaGetSymbolAddress((void**)&xlo,  g_xlo);
    cudaGetSymbolAddress((void**)&hhi,  g_hhi);
    cudaGetSymbolAddress((void**)&hlo,  g_hlo);
    cudaGetSymbolAddress((void**)&w,    g_w);
    cudaGetSymbolAddress((void**)&rowptr, g_rowptr);
    cudaGetSymbolAddress((void**)&cursor, g_cursor);
    cudaGetSymbolAddress((void**)&csr,    g_csr);
    cudaGetSymbolAddress((void**)&bsum,   g_bsum);
    cudaGetSymbolAddress((void**)&boff,   g_boff);

    __nv_bfloat16* w1l_hi = w;
    __nv_bfloat16* w1l_lo = w + 65536;
    __nv_bfloat16* w1r_hi = w + 2 * 65536;
    __nv_bfloat16* w1r_lo = w + 3 * 65536;
    __nv_bfloat16* w2_hi  = w + 4 * 65536;   // [W2l ; W2r] stacked
    __nv_bfloat16* w2_lo  = w + 5 * 65536;

    cudaFuncSetAttribute(gemm3, cudaFuncAttributeMaxDynamicSharedMemorySize, GEMM_SMEM);

    const int mb = (N + 127) / 128;
    const int nb = (N + SCAN_BLK - 1) / SCAN_BLK;

    cudaMemsetAsync(deg, 0, (size_t)N * sizeof(float));
    deg_kernel<<<(E + 255) / 256, 256>>>(dst, deg, E);                            // k1
    split_kernel<<<(N * (D1 / 4) + 255) / 256, 256>>>(x, xhi, xlo, N * (D1 / 4)); // k2
    wsplit_all<<<(49152 + 255) / 256, 256>>>(W1l, W1r, W2l, W2r, w);              // k3
    // k4 ← ncu-profiled slot: the GEMM
    gemm3<<<mb, 256, GEMM_SMEM>>>(xhi, xlo, w1l_hi, w1l_lo,
                                  y1, D1, nullptr, y1 + 128, D1, nullptr, N);     // k4
    scan_part<<<nb, 256>>>(deg, bsum, N);                                         // k5
    scan_sums<<<1, 128>>>(bsum, boff, nb);                                        // k6
    scan_write<<<nb, 256>>>(deg, boff, rowptr, cursor, N);                        // k7
    fill_csr<<<(E + 255) / 256, 256>>>(src, dst, cursor, csr, E);                 // k8
    gemm3<<<mb, 256, GEMM_SMEM>>>(xhi, xlo, w1r_hi, w1r_lo,
                                  z1, D1, b1, z1 + 128, D1, b1 + 128, N);         // k9
    gather1<<<(2 * N * 32 + 255) / 256, 256>>>(y1, z1, rowptr, csr, deg, hhi, hlo, N); // k10
    gemm3<<<mb, 256, GEMM_SMEM>>>(hhi, hlo, w2_hi, w2_lo,
                                  y2, D2, nullptr, z2, D2, b2, N);                // k11
    gather2<<<(N * 32 + 255) / 256, 256>>>(y2, z2, rowptr, csr, deg, out, N);     // k12
}